// round 2
// baseline (speedup 1.0000x reference)
#include <cuda_runtime.h>

#define B_  2048
#define E_  32
#define N_  32
#define D_  64
#define BE_ (B_*E_)

// One warp processes one (b,e) pair end-to-end:
//   scores -> softmax -> weighted mean of neighbors -> +self -> x@W^T+b -> relu
__global__ __launch_bounds__(256)
void sum_aggregator_kernel(const float* __restrict__ selfv,   // [B,E,D]
                           const float* __restrict__ nbv,     // [B,E,N,D]
                           const float* __restrict__ relv,    // [B,E,N,D]
                           const float* __restrict__ userv,   // [B,D]
                           const float* __restrict__ W,       // [D,D] row-major
                           const float* __restrict__ bl,      // [D]
                           float* __restrict__ out,           // [B,E,D]
                           int total_warps)
{
    // Interleaved W tile in smem:
    // Wq[k][l] = ( W[2l][2k], W[2l][2k+1], W[2l+1][2k], W[2l+1][2k+1] )
    // so lane l (outputs j=2l,2l+1) fetches one float4 per k-step, conflict-free.
    __shared__ float4 Wq[32][32];

    const int tid  = threadIdx.x;
    const int lane = tid & 31;
    const int wid  = tid >> 5;

    for (int i = tid; i < 32 * 32; i += 256) {
        int k = i >> 5, l = i & 31;
        Wq[k][l] = make_float4(W[(2*l  )*D_ + 2*k], W[(2*l  )*D_ + 2*k + 1],
                               W[(2*l+1)*D_ + 2*k], W[(2*l+1)*D_ + 2*k + 1]);
    }
    __syncthreads();

    const float2 bb = *reinterpret_cast<const float2*>(bl + 2*lane);
    const bool upper16 = (lane & 16) != 0;

    int gwarp = blockIdx.x * 8 + wid;
    for (int pair = gwarp; pair < BE_; pair += total_warps) {
        const int b = pair >> 5;  // / E_
        const float2 u = *reinterpret_cast<const float2*>(userv + (size_t)b*D_ + 2*lane);

        // ---- Pass 1: scores[n] = dot(user, rel[n,:]) / D ----
        // Load neighbor pair (k, k+16) and immediately fold the offset-16
        // butterfly stage, keeping only 16 live partials (register pressure).
        const float* relp = relv + (size_t)pair * (N_*D_);
        float w[16];
        #pragma unroll
        for (int k = 0; k < 16; k++) {
            float2 ra = __ldcs(reinterpret_cast<const float2*>(relp + k*D_       + 2*lane));
            float2 rb = __ldcs(reinterpret_cast<const float2*>(relp + (k+16)*D_  + 2*lane));
            float a = u.x * ra.x + u.y * ra.y;   // partial for neighbor k
            float c = u.x * rb.x + u.y * rb.y;   // partial for neighbor k+16
            float mine = upper16 ? c : a;
            float oth  = upper16 ? a : c;
            w[k] = mine + __shfl_xor_sync(0xffffffffu, oth, 16);
        }

        // Remaining reduce-scatter stages: lane n ends up owning score[n].
        #pragma unroll
        for (int off = 8; off >= 1; off >>= 1) {
            const bool up = (lane & off) != 0;
            #pragma unroll
            for (int k = 0; k < off; k++) {
                float mine = up ? w[off + k] : w[k];
                float oth  = up ? w[k]       : w[off + k];
                w[k] = mine + __shfl_xor_sync(0xffffffffu, oth, off);
            }
        }
        float s = w[0] * (1.0f / (float)D_);

        // ---- Softmax over n (value-per-lane) ----
        float m = s;
        #pragma unroll
        for (int off = 16; off >= 1; off >>= 1)
            m = fmaxf(m, __shfl_xor_sync(0xffffffffu, m, off));
        float e = __expf(s - m);
        float sum = e;
        #pragma unroll
        for (int off = 16; off >= 1; off >>= 1)
            sum += __shfl_xor_sync(0xffffffffu, sum, off);
        // fold the mean-over-N (1/32) into the attention weight
        const float a = e / (sum * (float)N_);

        // ---- Pass 2: agg = sum_n a[n] * nb[n,:] ----
        const float* nbp = nbv + (size_t)pair * (N_*D_);
        float2 acc0 = make_float2(0.f, 0.f);
        float2 acc1 = make_float2(0.f, 0.f);
        #pragma unroll
        for (int n = 0; n < N_; n += 2) {
            float an0 = __shfl_sync(0xffffffffu, a, n);
            float an1 = __shfl_sync(0xffffffffu, a, n + 1);
            float2 x0 = __ldcs(reinterpret_cast<const float2*>(nbp + n*D_     + 2*lane));
            float2 x1 = __ldcs(reinterpret_cast<const float2*>(nbp + (n+1)*D_ + 2*lane));
            acc0.x = fmaf(an0, x0.x, acc0.x);
            acc0.y = fmaf(an0, x0.y, acc0.y);
            acc1.x = fmaf(an1, x1.x, acc1.x);
            acc1.y = fmaf(an1, x1.y, acc1.y);
        }

        float2 sv = *reinterpret_cast<const float2*>(selfv + (size_t)pair*D_ + 2*lane);
        float2 o  = make_float2(sv.x + acc0.x + acc1.x, sv.y + acc0.y + acc1.y);

        // ---- Linear: y[j] = sum_d o[d] * W[j][d] + b[j], then relu ----
        float y0 = bb.x, y1 = bb.y;
        #pragma unroll
        for (int k = 0; k < 32; k++) {
            float ox = __shfl_sync(0xffffffffu, o.x, k);   // o[2k]
            float oy = __shfl_sync(0xffffffffu, o.y, k);   // o[2k+1]
            float4 wv = Wq[k][lane];
            y0 = fmaf(ox, wv.x, fmaf(oy, wv.y, y0));
            y1 = fmaf(ox, wv.z, fmaf(oy, wv.w, y1));
        }

        float2 res = make_float2(fmaxf(y0, 0.f), fmaxf(y1, 0.f));
        __stcs(reinterpret_cast<float2*>(out + (size_t)pair*D_ + 2*lane), res);
    }
}

extern "C" void kernel_launch(void* const* d_in, const int* in_sizes, int n_in,
                              void* d_out, int out_size)
{
    const float* selfv = (const float*)d_in[0];  // self_vectors      [B,E,D]
    const float* nbv   = (const float*)d_in[1];  // neighbor_vectors  [B,E,N,D]
    const float* relv  = (const float*)d_in[2];  // neighbor_relations[B,E,N,D]
    const float* userv = (const float*)d_in[3];  // user_embeddings   [B,D]
    // d_in[4] = masks (unused by the module)
    const float* W     = (const float*)d_in[5];  // [D,D]
    const float* bl    = (const float*)d_in[6];  // [D]
    float* out = (float*)d_out;

    // Size the grid to exactly the resident capacity (one logical wave,
    // grid-stride loop distributes 65536 pairs evenly +/-1).
    int dev = 0, sms = 148, occ = 0;
    cudaGetDevice(&dev);
    cudaDeviceGetAttribute(&sms, cudaDevAttrMultiProcessorCount, dev);
    cudaOccupancyMaxActiveBlocksPerMultiprocessor(&occ, sum_aggregator_kernel, 256, 0);
    if (occ < 1) occ = 1;
    int blocks = occ * sms;
    int max_blocks = BE_ / 8;            // never more warps than pairs
    if (blocks > max_blocks) blocks = max_blocks;
    int total_warps = blocks * 8;

    sum_aggregator_kernel<<<blocks, 256>>>(selfv, nbv, relv, userv, W, bl, out,
                                           total_warps);
}

// round 3
// speedup vs baseline: 1.0594x; 1.0594x over previous
#include <cuda_runtime.h>

#define B_  2048
#define E_  32
#define N_  32
#define D_  64
#define BE_ (B_*E_)

// One warp per (b,e) pair. Lane l covers dims [4q..4q+3] with q = l&15,
// half = l>>4. Each LDG.128 fetches TWO neighbor rows (512B per warp).
__global__ __launch_bounds__(256)
void sum_aggregator_kernel(const float* __restrict__ selfv,   // [B,E,D]
                           const float* __restrict__ nbv,     // [B,E,N,D]
                           const float* __restrict__ relv,    // [B,E,N,D]
                           const float* __restrict__ userv,   // [B,D]
                           const float* __restrict__ W,       // [D,D] row-major
                           const float* __restrict__ bl,      // [D]
                           float* __restrict__ out,           // [B,E,D]
                           int total_warps)
{
    // Wa[c][l] = W[2l][4c..4c+3], Wb[c][l] = W[2l+1][4c..4c+3]
    __shared__ float4 Wa[16][32];
    __shared__ float4 Wb[16][32];

    const int tid  = threadIdx.x;
    const int lane = tid & 31;
    const int wid  = tid >> 5;
    const int q    = lane & 15;

    for (int i = tid; i < 16 * 32; i += 256) {
        int c = i >> 5, l = i & 31;
        Wa[c][l] = *reinterpret_cast<const float4*>(W + (2*l  )*D_ + 4*c);
        Wb[c][l] = *reinterpret_cast<const float4*>(W + (2*l+1)*D_ + 4*c);
    }
    __syncthreads();

    const float2 bb = *reinterpret_cast<const float2*>(bl + 2*lane);

    int gwarp = blockIdx.x * 8 + wid;
    for (int pair = gwarp; pair < BE_; pair += total_warps) {
        const int b = pair >> 5;  // / E_
        const float4 u = *reinterpret_cast<const float4*>(userv + (size_t)b*D_ + 4*q);

        // ---- Pass 1: partial scores. Iter i loads neighbor rows (2i, 2i+1);
        // lane covers row 2i+half, dims 4q..4q+3. Sync-free load loop. ----
        const float* relp = relv + (size_t)pair * (N_*D_);
        float v[16];
        #pragma unroll
        for (int i = 0; i < 16; i++) {
            float4 r = *reinterpret_cast<const float4*>(relp + i*128 + 4*lane);
            v[i] = u.x*r.x + u.y*r.y + u.z*r.z + u.w*r.w;
        }

        // Reduce-scatter within each 16-lane half: lane ends owning the score
        // of neighbor n(l) = 2*(l&15) + (l>>4).
        #pragma unroll
        for (int off = 8; off >= 1; off >>= 1) {
            const bool up = (lane & off) != 0;
            #pragma unroll
            for (int k = 0; k < off; k++) {
                float mine = up ? v[off + k] : v[k];
                float oth  = up ? v[k]       : v[off + k];
                v[k] = mine + __shfl_xor_sync(0xffffffffu, oth, off);
            }
        }
        float s = v[0] * (1.0f / (float)D_);

        // ---- Softmax over 32 lanes (mapping-agnostic) ----
        float m = s;
        #pragma unroll
        for (int off = 16; off >= 1; off >>= 1)
            m = fmaxf(m, __shfl_xor_sync(0xffffffffu, m, off));
        float e = __expf(s - m);
        float sum = e;
        #pragma unroll
        for (int off = 16; off >= 1; off >>= 1)
            sum += __shfl_xor_sync(0xffffffffu, sum, off);
        const float a = e / (sum * (float)N_);   // weight of neighbor n(l), /N folded

        // ---- Pass 2: agg. Iter i loads rows (2i, 2i+1); weight for the
        // lane's row lives at lane i + (lane & 16). ----
        const float* nbp = nbv + (size_t)pair * (N_*D_);
        float4 acc = make_float4(0.f, 0.f, 0.f, 0.f);
        #pragma unroll
        for (int i = 0; i < 16; i++) {
            float4 x = *reinterpret_cast<const float4*>(nbp + i*128 + 4*lane);
            float an = __shfl_sync(0xffffffffu, a, i + (lane & 16));
            acc.x = fmaf(an, x.x, acc.x);
            acc.y = fmaf(an, x.y, acc.y);
            acc.z = fmaf(an, x.z, acc.z);
            acc.w = fmaf(an, x.w, acc.w);
        }
        // Fold even/odd halves: every lane gets full agg for dims 4q..4q+3.
        acc.x += __shfl_xor_sync(0xffffffffu, acc.x, 16);
        acc.y += __shfl_xor_sync(0xffffffffu, acc.y, 16);
        acc.z += __shfl_xor_sync(0xffffffffu, acc.z, 16);
        acc.w += __shfl_xor_sync(0xffffffffu, acc.w, 16);

        const float4 sv = *reinterpret_cast<const float4*>(selfv + (size_t)pair*D_ + 4*q);
        float4 o = make_float4(sv.x + acc.x, sv.y + acc.y, sv.z + acc.z, sv.w + acc.w);

        // ---- Linear: y[j] = b[j] + sum_d o[d]*W[j][d], j = 2*lane, 2*lane+1 ----
        float y0 = bb.x, y1 = bb.y;
        #pragma unroll
        for (int c = 0; c < 16; c++) {
            float ox = __shfl_sync(0xffffffffu, o.x, c);
            float oy = __shfl_sync(0xffffffffu, o.y, c);
            float oz = __shfl_sync(0xffffffffu, o.z, c);
            float ow = __shfl_sync(0xffffffffu, o.w, c);
            float4 wa = Wa[c][lane];
            float4 wb = Wb[c][lane];
            y0 = fmaf(ox, wa.x, fmaf(oy, wa.y, fmaf(oz, wa.z, fmaf(ow, wa.w, y0))));
            y1 = fmaf(ox, wb.x, fmaf(oy, wb.y, fmaf(oz, wb.z, fmaf(ow, wb.w, y1))));
        }

        float2 res = make_float2(fmaxf(y0, 0.f), fmaxf(y1, 0.f));
        *reinterpret_cast<float2*>(out + (size_t)pair*D_ + 2*lane) = res;
    }
}

extern "C" void kernel_launch(void* const* d_in, const int* in_sizes, int n_in,
                              void* d_out, int out_size)
{
    const float* selfv = (const float*)d_in[0];  // self_vectors      [B,E,D]
    const float* nbv   = (const float*)d_in[1];  // neighbor_vectors  [B,E,N,D]
    const float* relv  = (const float*)d_in[2];  // neighbor_relations[B,E,N,D]
    const float* userv = (const float*)d_in[3];  // user_embeddings   [B,D]
    // d_in[4] = masks (unused)
    const float* W     = (const float*)d_in[5];  // [D,D]
    const float* bl    = (const float*)d_in[6];  // [D]
    float* out = (float*)d_out;

    int dev = 0, sms = 148, occ = 0;
    cudaGetDevice(&dev);
    cudaDeviceGetAttribute(&sms, cudaDevAttrMultiProcessorCount, dev);
    cudaOccupancyMaxActiveBlocksPerMultiprocessor(&occ, sum_aggregator_kernel, 256, 0);
    if (occ < 1) occ = 1;
    if (occ > 4) occ = 4;                // cap: 32 warps/SM measured best (R1 vs R2)
    int blocks = occ * sms;
    int max_blocks = BE_ / 8;
    if (blocks > max_blocks) blocks = max_blocks;
    int total_warps = blocks * 8;

    sum_aggregator_kernel<<<blocks, 256>>>(selfv, nbv, relv, userv, W, bl, out,
                                           total_warps);
}